// round 4
// baseline (speedup 1.0000x reference)
#include <cuda_runtime.h>
#include <cuda_fp16.h>
#include <cstdint>

// Problem constants (fixed by dataset)
#define Nn 50000
#define Dd 128
#define Rr 3
#define Ee 800000
#define OUTD 64
#define ALPHAc 0.5f
#define BETA1c 0.6931471805599453f   // ln 2
#define BETA2c 0.4054651081081644f   // ln 1.5
#define SLOPEc 0.01f

// ---------------- scratch (device globals; no allocations allowed) ----------
__device__ __align__(16) __half g_xs [(size_t)Rr * Nn * Dd];  // 38.4 MB prescaled x
__device__ __align__(16) __half g_h1s[(size_t)Rr * Nn * Dd];  // 38.4 MB prescaled h1
__device__ int   g_deg_out[Rr * Nn];
__device__ int   g_deg_in[Rr * Nn];
__device__ float g_dinv_out[Rr * Nn];
__device__ float g_dinv_in[Rr * Nn];
__device__ int   g_rowstart[Rr * Nn];
__device__ int   g_fillcur[Rr * Nn];
__device__ int   g_col[(size_t)Rr * Ee];         // 9.6 MB
__device__ int   g_cursor[Rr];
__device__ float g_G[Rr * Dd * OUTD];            // (1-a)/3 * M2_r
__device__ float g_Gx[Dd * OUTD];                // a/3 * sum_r M2_r
__device__ float g_c[OUTD];

// ---------------- init small state -------------------------------------------
__global__ void k_init() {
    int i = blockIdx.x * blockDim.x + threadIdx.x;
    if (i < Rr * Nn) { g_deg_out[i] = 0; g_deg_in[i] = 0; }
    if (i < Rr) g_cursor[i] = 0;
}

// ---------------- degree histogram -------------------------------------------
__global__ void k_degree(const int* __restrict__ src, const int* __restrict__ dst) {
    int i = blockIdx.x * blockDim.x + threadIdx.x;
    if (i >= Rr * Ee) return;
    int r = i / Ee;
    atomicAdd(&g_deg_out[r * Nn + src[i]], 1);
    atomicAdd(&g_deg_in [r * Nn + dst[i]], 1);
}

// ---------------- row starts via warp-aggregated scan + dinv ------------------
__global__ void k_rowstart() {
    int r = blockIdx.y;
    int n = blockIdx.x * blockDim.x + threadIdx.x;
    int lane = threadIdx.x & 31;
    int d = (n < Nn) ? g_deg_in[r * Nn + n] : 0;
    int incl = d;
#pragma unroll
    for (int o = 1; o < 32; o <<= 1) {
        int v = __shfl_up_sync(0xffffffffu, incl, o);
        if (lane >= o) incl += v;
    }
    int total = __shfl_sync(0xffffffffu, incl, 31);
    int base = 0;
    if (lane == 31) base = atomicAdd(&g_cursor[r], total);
    base = __shfl_sync(0xffffffffu, base, 31);
    if (n < Nn) {
        int start = r * Ee + base + incl - d;
        g_rowstart[r * Nn + n] = start;
        g_fillcur [r * Nn + n] = start;
        int di = d < 1 ? 1 : d;
        g_dinv_in[r * Nn + n] = rsqrtf((float)di);
        int doo = g_deg_out[r * Nn + n]; if (doo < 1) doo = 1;
        g_dinv_out[r * Nn + n] = rsqrtf((float)doo);
    }
}

// ---------------- CSR fill -----------------------------------------------------
__global__ void k_csrfill(const int* __restrict__ src, const int* __restrict__ dst) {
    int i = blockIdx.x * blockDim.x + threadIdx.x;
    if (i >= Rr * Ee) return;
    int r = i / Ee;
    int pos = atomicAdd(&g_fillcur[r * Nn + dst[i]], 1);
    g_col[pos] = src[i];
}

// ---------------- prescale x into fp16 gather operands ------------------------
// g_xs[r][n][:] = half( x[n][:] * dinv_out[r][n] )
__global__ void k_prescale(const float* __restrict__ x) {
    size_t i = (size_t)blockIdx.x * blockDim.x + threadIdx.x;   // one per 4 elems
    if (i >= (size_t)Rr * Nn * (Dd / 4)) return;
    int c4 = (int)(i & 31);
    size_t rn = i >> 5;
    int n = (int)(rn % Nn);
    int r = (int)(rn / Nn);
    float s = g_dinv_out[r * Nn + n];
    float4 v = __ldg(reinterpret_cast<const float4*>(x + (size_t)n * Dd) + c4);
    __half2 p0 = __floats2half2_rn(v.x * s, v.y * s);
    __half2 p1 = __floats2half2_rn(v.z * s, v.w * s);
    uint2 u;
    u.x = *reinterpret_cast<unsigned*>(&p0);
    u.y = *reinterpret_cast<unsigned*>(&p1);
    *reinterpret_cast<uint2*>(g_xs + rn * Dd + c4 * 4) = u;
}

// ---------------- precompute folded layer-2 matrices --------------------------
__global__ void k_prep1(const float* __restrict__ W2, const float* __restrict__ Wlin) {
    int r = blockIdx.x >> 7;
    int i = blockIdx.x & 127;
    int j = threadIdx.x;              // 0..63
    const float* wrow = W2 + ((size_t)r * Dd + i) * Dd;
    float s = 0.f;
#pragma unroll 8
    for (int k = 0; k < Dd; ++k) s += wrow[k] * Wlin[k * OUTD + j];
    g_G[((size_t)r * Dd + i) * OUTD + j] = BETA2c * s + (1.f - BETA2c) * Wlin[i * OUTD + j];
}

__global__ void k_prep2(const float* __restrict__ b2, const float* __restrict__ Wlin,
                        const float* __restrict__ blin) {
    int idx = blockIdx.x * blockDim.x + threadIdx.x;
    if (idx < Dd * OUTD) {
        float s = g_G[idx] + g_G[Dd * OUTD + idx] + g_G[2 * Dd * OUTD + idx];
        g_Gx[idx] = (ALPHAc / 3.f) * s;
        const float sc = (1.f - ALPHAc) / 3.f;
        g_G[idx] *= sc;
        g_G[Dd * OUTD + idx] *= sc;
        g_G[2 * Dd * OUTD + idx] *= sc;
    }
    if (idx < OUTD) {
        float cc = blin[idx];
        for (int k = 0; k < Dd; ++k)
            cc += (b2[k] + b2[Dd + k] + b2[2 * Dd + k]) * (1.f / 3.f) * Wlin[k * OUTD + idx];
        g_c[idx] = cc;
    }
}

// ---------------- fp16 gather: acc += half4 row chunks ------------------------
__device__ __forceinline__ void acc_h4(float4& acc, uint2 u) {
    __half2 a = *reinterpret_cast<__half2*>(&u.x);
    __half2 b = *reinterpret_cast<__half2*>(&u.y);
    float2 fa = __half22float2(a), fb = __half22float2(b);
    acc.x += fa.x; acc.y += fa.y; acc.z += fb.x; acc.w += fb.y;
}

__device__ __forceinline__ float4 gather_half(const __half* __restrict__ base,
                                              int beg, int end, int lane) {
    float4 acc = make_float4(0.f, 0.f, 0.f, 0.f);
    int e = beg;
#pragma unroll 1
    for (; e + 4 <= end; e += 4) {
        int s0 = __ldg(g_col + e);
        int s1 = __ldg(g_col + e + 1);
        int s2 = __ldg(g_col + e + 2);
        int s3 = __ldg(g_col + e + 3);
        uint2 u0 = __ldg(reinterpret_cast<const uint2*>(base + (size_t)s0 * Dd) + lane);
        uint2 u1 = __ldg(reinterpret_cast<const uint2*>(base + (size_t)s1 * Dd) + lane);
        uint2 u2 = __ldg(reinterpret_cast<const uint2*>(base + (size_t)s2 * Dd) + lane);
        uint2 u3 = __ldg(reinterpret_cast<const uint2*>(base + (size_t)s3 * Dd) + lane);
        acc_h4(acc, u0); acc_h4(acc, u1); acc_h4(acc, u2); acc_h4(acc, u3);
    }
#pragma unroll 1
    for (; e < end; ++e) {
        int s0 = __ldg(g_col + e);
        uint2 u0 = __ldg(reinterpret_cast<const uint2*>(base + (size_t)s0 * Dd) + lane);
        acc_h4(acc, u0);
    }
    return acc;
}

// pack 8 scaled floats -> 8 halfs (16B)
__device__ __forceinline__ uint4 pack_half8(const float* v, float s) {
    __half2 p0 = __floats2half2_rn(v[0] * s, v[1] * s);
    __half2 p1 = __floats2half2_rn(v[2] * s, v[3] * s);
    __half2 p2 = __floats2half2_rn(v[4] * s, v[5] * s);
    __half2 p3 = __floats2half2_rn(v[6] * s, v[7] * s);
    uint4 u;
    u.x = *reinterpret_cast<unsigned*>(&p0);
    u.y = *reinterpret_cast<unsigned*>(&p1);
    u.z = *reinterpret_cast<unsigned*>(&p2);
    u.w = *reinterpret_cast<unsigned*>(&p3);
    return u;
}

// ---------------- layer-1: fused gather + GEMM --------------------------------
// gather prescaled xs; GEMM vs W1; epilogue writes prescaled fp16 h1s (3 copies)
__launch_bounds__(256)
__global__ void k_node1(const float* __restrict__ x, const float* __restrict__ W1,
                        const float* __restrict__ b1) {
    __shared__ float As[64 * 132];
    __shared__ float Ws[16 * 128];
    int tid = threadIdx.x;
    int warp = tid >> 5, lane = tid & 31;
    int ty = tid >> 4, tx = tid & 15;
    int n0 = blockIdx.x << 6;

    float hacc[4][8];
#pragma unroll
    for (int i = 0; i < 4; ++i)
#pragma unroll
        for (int j = 0; j < 8; ++j) hacc[i][j] = 0.f;

    for (int r = 0; r < Rr; ++r) {
        // ---- fused gather: build As = rst
#pragma unroll 1
        for (int ii = 0; ii < 8; ++ii) {
            int row = warp * 8 + ii;
            int n = n0 + row;
            float4 v = make_float4(0.f, 0.f, 0.f, 0.f);
            if (n < Nn) {
                int beg = g_rowstart[r * Nn + n];
                int end = beg + g_deg_in[r * Nn + n];
                float4 acc = gather_half(g_xs + (size_t)r * Nn * Dd, beg, end, lane);
                float di = g_dinv_in[r * Nn + n] * (1.f - ALPHAc);
                float4 xv = __ldg(reinterpret_cast<const float4*>(x + (size_t)n * Dd) + lane);
                v.x = di * acc.x + ALPHAc * xv.x;
                v.y = di * acc.y + ALPHAc * xv.y;
                v.z = di * acc.z + ALPHAc * xv.z;
                v.w = di * acc.w + ALPHAc * xv.w;
            }
            *reinterpret_cast<float4*>(&As[row * 132 + lane * 4]) = v;
        }
        __syncthreads();

        // ---- register-blocked GEMM: rst @ W1_r
        float acc[4][8];
#pragma unroll
        for (int i = 0; i < 4; ++i)
#pragma unroll
            for (int j = 0; j < 8; ++j) acc[i][j] = 0.f;

        for (int kc = 0; kc < 8; ++kc) {
            for (int idx = tid; idx < 16 * 32; idx += 256) {
                int kr = idx >> 5, c4 = idx & 31;
                reinterpret_cast<float4*>(&Ws[kr * 128])[c4] =
                    reinterpret_cast<const float4*>(W1 + ((size_t)r * Dd + kc * 16 + kr) * Dd)[c4];
            }
            __syncthreads();
#pragma unroll
            for (int k = 0; k < 16; ++k) {
                float a[4];
#pragma unroll
                for (int i = 0; i < 4; ++i) a[i] = As[(ty * 4 + i) * 132 + kc * 16 + k];
                float4 w0 = *reinterpret_cast<float4*>(&Ws[k * 128 + tx * 8]);
                float4 w1 = *reinterpret_cast<float4*>(&Ws[k * 128 + tx * 8 + 4]);
#pragma unroll
                for (int i = 0; i < 4; ++i) {
                    acc[i][0] += a[i] * w0.x; acc[i][1] += a[i] * w0.y;
                    acc[i][2] += a[i] * w0.z; acc[i][3] += a[i] * w0.w;
                    acc[i][4] += a[i] * w1.x; acc[i][5] += a[i] * w1.y;
                    acc[i][6] += a[i] * w1.z; acc[i][7] += a[i] * w1.w;
                }
            }
            __syncthreads();
        }

        // epilogue: identity mapping + bias + leaky_relu + 1/3 mean
#pragma unroll
        for (int i = 0; i < 4; ++i) {
            int row = ty * 4 + i;
#pragma unroll
            for (int j = 0; j < 8; ++j) {
                int col = tx * 8 + j;
                float v = BETA1c * acc[i][j] + (1.f - BETA1c) * As[row * 132 + col]
                          + b1[r * Dd + col];
                v = v >= 0.f ? v : SLOPEc * v;
                hacc[i][j] += v * (1.f / 3.f);
            }
        }
        __syncthreads();
    }

    // write prescaled fp16 h1s for each relation
#pragma unroll
    for (int i = 0; i < 4; ++i) {
        int n = n0 + ty * 4 + i;
        if (n < Nn) {
#pragma unroll
            for (int r = 0; r < Rr; ++r) {
                float s = g_dinv_out[r * Nn + n];
                uint4 u = pack_half8(hacc[i], s);
                *reinterpret_cast<uint4*>(g_h1s + ((size_t)r * Nn + n) * Dd + tx * 8) = u;
            }
        }
    }
}

// ---------------- layer-2 + output projection, fused gather -------------------
__launch_bounds__(256)
__global__ void k_node2(const float* __restrict__ x, float* __restrict__ out) {
    __shared__ float As[64 * 132];
    __shared__ float Ws[16 * 64];
    int tid = threadIdx.x;
    int warp = tid >> 5, lane = tid & 31;
    int ty = tid >> 4, tx = tid & 15;
    int n0 = blockIdx.x << 6;

    float acc[4][4];
#pragma unroll
    for (int i = 0; i < 4; ++i)
#pragma unroll
        for (int j = 0; j < 4; ++j) acc[i][j] = 0.f;

    for (int seg = 0; seg < 4; ++seg) {
#pragma unroll 1
        for (int ii = 0; ii < 8; ++ii) {
            int row = warp * 8 + ii;
            int n = n0 + row;
            float4 v = make_float4(0.f, 0.f, 0.f, 0.f);
            if (n < Nn) {
                if (seg < 3) {
                    int r = seg;
                    int beg = g_rowstart[r * Nn + n];
                    int end = beg + g_deg_in[r * Nn + n];
                    float4 a = gather_half(g_h1s + (size_t)r * Nn * Dd, beg, end, lane);
                    float di = g_dinv_in[r * Nn + n];
                    v.x = a.x * di; v.y = a.y * di; v.z = a.z * di; v.w = a.w * di;
                } else {
                    v = __ldg(reinterpret_cast<const float4*>(x + (size_t)n * Dd) + lane);
                }
            }
            *reinterpret_cast<float4*>(&As[row * 132 + lane * 4]) = v;
        }
        __syncthreads();

        const float* B = (seg < 3) ? (const float*)(g_G + (size_t)seg * Dd * OUTD)
                                   : (const float*)g_Gx;
        for (int kc = 0; kc < 8; ++kc) {
            {
                int kr = tid >> 4, c4 = tid & 15;   // 256 threads == 256 float4s
                reinterpret_cast<float4*>(&Ws[kr * 64])[c4] =
                    reinterpret_cast<const float4*>(B + (size_t)(kc * 16 + kr) * OUTD)[c4];
            }
            __syncthreads();
#pragma unroll
            for (int k = 0; k < 16; ++k) {
                float a[4];
#pragma unroll
                for (int i = 0; i < 4; ++i) a[i] = As[(ty * 4 + i) * 132 + kc * 16 + k];
                float4 w = *reinterpret_cast<float4*>(&Ws[k * 64 + tx * 4]);
#pragma unroll
                for (int i = 0; i < 4; ++i) {
                    acc[i][0] += a[i] * w.x; acc[i][1] += a[i] * w.y;
                    acc[i][2] += a[i] * w.z; acc[i][3] += a[i] * w.w;
                }
            }
            __syncthreads();
        }
    }

#pragma unroll
    for (int i = 0; i < 4; ++i) {
        int n = n0 + ty * 4 + i;
        if (n < Nn) {
            float4 o;
            o.x = acc[i][0] + g_c[tx * 4 + 0];
            o.y = acc[i][1] + g_c[tx * 4 + 1];
            o.z = acc[i][2] + g_c[tx * 4 + 2];
            o.w = acc[i][3] + g_c[tx * 4 + 3];
            *reinterpret_cast<float4*>(out + (size_t)n * OUTD + tx * 4) = o;
        }
    }
}

// ---------------- launch ------------------------------------------------------
extern "C" void kernel_launch(void* const* d_in, const int* in_sizes, int n_in,
                              void* d_out, int out_size) {
    const float* x    = (const float*)d_in[0];
    const int*   src  = (const int*)  d_in[1];
    const int*   dst  = (const int*)  d_in[2];
    const float* W1   = (const float*)d_in[3];
    const float* b1   = (const float*)d_in[4];
    const float* W2   = (const float*)d_in[5];
    const float* b2   = (const float*)d_in[6];
    const float* Wlin = (const float*)d_in[7];
    const float* blin = (const float*)d_in[8];
    float* out = (float*)d_out;

    k_init<<<(Rr * Nn + 255) / 256, 256>>>();
    k_degree<<<(Rr * Ee + 255) / 256, 256>>>(src, dst);
    dim3 rsgrid((Nn + 255) / 256, Rr);
    k_rowstart<<<rsgrid, 256>>>();
    k_csrfill<<<(Rr * Ee + 255) / 256, 256>>>(src, dst);
    k_prescale<<<(int)(((size_t)Rr * Nn * (Dd / 4) + 255) / 256), 256>>>(x);
    k_prep1<<<Rr * Dd, OUTD>>>(W2, Wlin);
    k_prep2<<<32, 256>>>(b2, Wlin, blin);

    k_node1<<<(Nn + 63) / 64, 256>>>(x, W1, b1);
    k_node2<<<(Nn + 63) / 64, 256>>>(x, out);
}

// round 5
// speedup vs baseline: 1.1725x; 1.1725x over previous
#include <cuda_runtime.h>
#include <cuda_fp16.h>
#include <cstdint>

// Problem constants (fixed by dataset)
#define Nn 50000
#define Dd 128
#define Rr 3
#define Ee 800000
#define OUTD 64
#define ALPHAc 0.5f
#define BETA1c 0.6931471805599453f   // ln 2
#define BETA2c 0.4054651081081644f   // ln 1.5
#define SLOPEc 0.01f

// ---------------- scratch (device globals; no allocations allowed) ----------
__device__ __align__(16) __half g_xs [(size_t)Rr * Nn * Dd];  // 38.4 MB prescaled x (fp16)
__device__ __align__(16) __half g_h1s[(size_t)Rr * Nn * Dd];  // 38.4 MB prescaled h1 (fp16)
__device__ __align__(16) float  g_agg[(size_t)Rr * Nn * Dd];  // 76.8 MB gather output (reused)
__device__ int   g_deg_out[Rr * Nn];
__device__ int   g_deg_in[Rr * Nn];
__device__ float g_dinv_out[Rr * Nn];
__device__ float g_dinv_in[Rr * Nn];
__device__ int   g_rowstart[Rr * Nn];
__device__ int   g_fillcur[Rr * Nn];
__device__ int   g_col[(size_t)Rr * Ee];         // 9.6 MB
__device__ int   g_cursor[Rr];
__device__ float g_G[Rr * Dd * OUTD];            // (1-a)/3 * M2_r
__device__ float g_Gx[Dd * OUTD];                // a/3 * sum_r M2_r
__device__ float g_c[OUTD];

// ---------------- init small state -------------------------------------------
__global__ void k_init() {
    int i = blockIdx.x * blockDim.x + threadIdx.x;
    if (i < Rr * Nn) { g_deg_out[i] = 0; g_deg_in[i] = 0; }
    if (i < Rr) g_cursor[i] = 0;
}

// ---------------- degree histogram -------------------------------------------
__global__ void k_degree(const int* __restrict__ src, const int* __restrict__ dst) {
    int i = blockIdx.x * blockDim.x + threadIdx.x;
    if (i >= Rr * Ee) return;
    int r = i / Ee;
    atomicAdd(&g_deg_out[r * Nn + src[i]], 1);
    atomicAdd(&g_deg_in [r * Nn + dst[i]], 1);
}

// ---------------- row starts via warp-aggregated scan + dinv ------------------
__global__ void k_rowstart() {
    int r = blockIdx.y;
    int n = blockIdx.x * blockDim.x + threadIdx.x;
    int lane = threadIdx.x & 31;
    int d = (n < Nn) ? g_deg_in[r * Nn + n] : 0;
    int incl = d;
#pragma unroll
    for (int o = 1; o < 32; o <<= 1) {
        int v = __shfl_up_sync(0xffffffffu, incl, o);
        if (lane >= o) incl += v;
    }
    int total = __shfl_sync(0xffffffffu, incl, 31);
    int base = 0;
    if (lane == 31) base = atomicAdd(&g_cursor[r], total);
    base = __shfl_sync(0xffffffffu, base, 31);
    if (n < Nn) {
        int start = r * Ee + base + incl - d;
        g_rowstart[r * Nn + n] = start;
        g_fillcur [r * Nn + n] = start;
        int di = d < 1 ? 1 : d;
        g_dinv_in[r * Nn + n] = rsqrtf((float)di);
        int doo = g_deg_out[r * Nn + n]; if (doo < 1) doo = 1;
        g_dinv_out[r * Nn + n] = rsqrtf((float)doo);
    }
}

// ---------------- CSR fill -----------------------------------------------------
__global__ void k_csrfill(const int* __restrict__ src, const int* __restrict__ dst) {
    int i = blockIdx.x * blockDim.x + threadIdx.x;
    if (i >= Rr * Ee) return;
    int r = i / Ee;
    int pos = atomicAdd(&g_fillcur[r * Nn + dst[i]], 1);
    g_col[pos] = src[i];
}

// ---------------- prescale x into fp16 gather operands ------------------------
__global__ void k_prescale(const float* __restrict__ x) {
    size_t i = (size_t)blockIdx.x * blockDim.x + threadIdx.x;   // one per 4 elems
    if (i >= (size_t)Rr * Nn * (Dd / 4)) return;
    int c4 = (int)(i & 31);
    size_t rn = i >> 5;
    int n = (int)(rn % Nn);
    int r = (int)(rn / Nn);
    float s = g_dinv_out[r * Nn + n];
    float4 v = __ldg(reinterpret_cast<const float4*>(x + (size_t)n * Dd) + c4);
    __half2 p0 = __floats2half2_rn(v.x * s, v.y * s);
    __half2 p1 = __floats2half2_rn(v.z * s, v.w * s);
    uint2 u;
    u.x = *reinterpret_cast<unsigned*>(&p0);
    u.y = *reinterpret_cast<unsigned*>(&p1);
    *reinterpret_cast<uint2*>(g_xs + rn * Dd + c4 * 4) = u;
}

// ---------------- precompute folded layer-2 matrices --------------------------
__global__ void k_prep1(const float* __restrict__ W2, const float* __restrict__ Wlin) {
    int r = blockIdx.x >> 7;
    int i = blockIdx.x & 127;
    int j = threadIdx.x;              // 0..63
    const float* wrow = W2 + ((size_t)r * Dd + i) * Dd;
    float s = 0.f;
#pragma unroll 8
    for (int k = 0; k < Dd; ++k) s += wrow[k] * Wlin[k * OUTD + j];
    g_G[((size_t)r * Dd + i) * OUTD + j] = BETA2c * s + (1.f - BETA2c) * Wlin[i * OUTD + j];
}

__global__ void k_prep2(const float* __restrict__ b2, const float* __restrict__ Wlin,
                        const float* __restrict__ blin) {
    int idx = blockIdx.x * blockDim.x + threadIdx.x;
    if (idx < Dd * OUTD) {
        float s = g_G[idx] + g_G[Dd * OUTD + idx] + g_G[2 * Dd * OUTD + idx];
        g_Gx[idx] = (ALPHAc / 3.f) * s;
        const float sc = (1.f - ALPHAc) / 3.f;
        g_G[idx] *= sc;
        g_G[Dd * OUTD + idx] *= sc;
        g_G[2 * Dd * OUTD + idx] *= sc;
    }
    if (idx < OUTD) {
        float cc = blin[idx];
        for (int k = 0; k < Dd; ++k)
            cc += (b2[k] + b2[Dd + k] + b2[2 * Dd + k]) * (1.f / 3.f) * Wlin[k * OUTD + idx];
        g_c[idx] = cc;
    }
}

// ---------------- fp16 gather helpers ------------------------------------------
__device__ __forceinline__ void acc_h4(float4& acc, uint2 u) {
    __half2 a = *reinterpret_cast<__half2*>(&u.x);
    __half2 b = *reinterpret_cast<__half2*>(&u.y);
    float2 fa = __half22float2(a), fb = __half22float2(b);
    acc.x += fa.x; acc.y += fa.y; acc.z += fb.x; acc.w += fb.y;
}

// ---------------- dedicated gather kernel: one warp per (r,n) row --------------
// agg[r][n][:] = sum_e half_rows[col[e]][:]   (rows already prescaled by dinv_out)
__launch_bounds__(256)
__global__ void k_gather(int which) {
    int gw = (blockIdx.x * blockDim.x + threadIdx.x) >> 5;   // (r,n) index
    if (gw >= Rr * Nn) return;
    int lane = threadIdx.x & 31;
    const __half* base = (which ? g_h1s : g_xs) + (size_t)(gw / Nn) * Nn * Dd;

    int beg = __ldg(g_rowstart + gw);
    int end = beg + __ldg(g_deg_in + gw);
    float4 acc = make_float4(0.f, 0.f, 0.f, 0.f);
    int e = beg;
#pragma unroll 1
    for (; e + 4 <= end; e += 4) {
        int s0 = __ldg(g_col + e);
        int s1 = __ldg(g_col + e + 1);
        int s2 = __ldg(g_col + e + 2);
        int s3 = __ldg(g_col + e + 3);
        uint2 u0 = __ldg(reinterpret_cast<const uint2*>(base + (size_t)s0 * Dd) + lane);
        uint2 u1 = __ldg(reinterpret_cast<const uint2*>(base + (size_t)s1 * Dd) + lane);
        uint2 u2 = __ldg(reinterpret_cast<const uint2*>(base + (size_t)s2 * Dd) + lane);
        uint2 u3 = __ldg(reinterpret_cast<const uint2*>(base + (size_t)s3 * Dd) + lane);
        acc_h4(acc, u0); acc_h4(acc, u1); acc_h4(acc, u2); acc_h4(acc, u3);
    }
#pragma unroll 1
    for (; e < end; ++e) {
        int s0 = __ldg(g_col + e);
        uint2 u0 = __ldg(reinterpret_cast<const uint2*>(base + (size_t)s0 * Dd) + lane);
        acc_h4(acc, u0);
    }
    *reinterpret_cast<float4*>(g_agg + (size_t)gw * Dd + lane * 4) = acc;
}

// pack 8 scaled floats -> 8 halfs (16B)
__device__ __forceinline__ uint4 pack_half8(const float* v, float s) {
    __half2 p0 = __floats2half2_rn(v[0] * s, v[1] * s);
    __half2 p1 = __floats2half2_rn(v[2] * s, v[3] * s);
    __half2 p2 = __floats2half2_rn(v[4] * s, v[5] * s);
    __half2 p3 = __floats2half2_rn(v[6] * s, v[7] * s);
    uint4 u;
    u.x = *reinterpret_cast<unsigned*>(&p0);
    u.y = *reinterpret_cast<unsigned*>(&p1);
    u.z = *reinterpret_cast<unsigned*>(&p2);
    u.w = *reinterpret_cast<unsigned*>(&p3);
    return u;
}

// ---------------- layer-1 GEMM (reads contiguous agg) --------------------------
__launch_bounds__(256)
__global__ void k_gemm1(const float* __restrict__ x, const float* __restrict__ W1,
                        const float* __restrict__ b1) {
    __shared__ float As[64 * 132];
    __shared__ float Ws[16 * 128];
    int tid = threadIdx.x;
    int ty = tid >> 4, tx = tid & 15;
    int n0 = blockIdx.x << 6;

    float hacc[4][8];
#pragma unroll
    for (int i = 0; i < 4; ++i)
#pragma unroll
        for (int j = 0; j < 8; ++j) hacc[i][j] = 0.f;

    for (int r = 0; r < Rr; ++r) {
        // build As = rst = (1-a)*dinv_in*agg + a*x  (contiguous reads)
        for (int idx = tid; idx < 64 * 32; idx += 256) {
            int row = idx >> 5, c4 = idx & 31;
            int n = n0 + row;
            float4 v = make_float4(0.f, 0.f, 0.f, 0.f);
            if (n < Nn) {
                float di = __ldg(g_dinv_in + r * Nn + n) * (1.f - ALPHAc);
                float4 a = __ldg(reinterpret_cast<const float4*>(g_agg + ((size_t)(r * Nn + n)) * Dd) + c4);
                float4 xv = __ldg(reinterpret_cast<const float4*>(x + (size_t)n * Dd) + c4);
                v.x = di * a.x + ALPHAc * xv.x;
                v.y = di * a.y + ALPHAc * xv.y;
                v.z = di * a.z + ALPHAc * xv.z;
                v.w = di * a.w + ALPHAc * xv.w;
            }
            *reinterpret_cast<float4*>(&As[row * 132 + c4 * 4]) = v;
        }
        __syncthreads();

        float acc[4][8];
#pragma unroll
        for (int i = 0; i < 4; ++i)
#pragma unroll
            for (int j = 0; j < 8; ++j) acc[i][j] = 0.f;

        for (int kc = 0; kc < 8; ++kc) {
            for (int idx = tid; idx < 16 * 32; idx += 256) {
                int kr = idx >> 5, c4 = idx & 31;
                reinterpret_cast<float4*>(&Ws[kr * 128])[c4] =
                    reinterpret_cast<const float4*>(W1 + ((size_t)r * Dd + kc * 16 + kr) * Dd)[c4];
            }
            __syncthreads();
#pragma unroll
            for (int k = 0; k < 16; ++k) {
                float a[4];
#pragma unroll
                for (int i = 0; i < 4; ++i) a[i] = As[(ty * 4 + i) * 132 + kc * 16 + k];
                float4 w0 = *reinterpret_cast<float4*>(&Ws[k * 128 + tx * 8]);
                float4 w1 = *reinterpret_cast<float4*>(&Ws[k * 128 + tx * 8 + 4]);
#pragma unroll
                for (int i = 0; i < 4; ++i) {
                    acc[i][0] += a[i] * w0.x; acc[i][1] += a[i] * w0.y;
                    acc[i][2] += a[i] * w0.z; acc[i][3] += a[i] * w0.w;
                    acc[i][4] += a[i] * w1.x; acc[i][5] += a[i] * w1.y;
                    acc[i][6] += a[i] * w1.z; acc[i][7] += a[i] * w1.w;
                }
            }
            __syncthreads();
        }

#pragma unroll
        for (int i = 0; i < 4; ++i) {
            int row = ty * 4 + i;
#pragma unroll
            for (int j = 0; j < 8; ++j) {
                int col = tx * 8 + j;
                float v = BETA1c * acc[i][j] + (1.f - BETA1c) * As[row * 132 + col]
                          + b1[r * Dd + col];
                v = v >= 0.f ? v : SLOPEc * v;
                hacc[i][j] += v * (1.f / 3.f);
            }
        }
        __syncthreads();
    }

    // write prescaled fp16 h1s for each relation
#pragma unroll
    for (int i = 0; i < 4; ++i) {
        int n = n0 + ty * 4 + i;
        if (n < Nn) {
#pragma unroll
            for (int r = 0; r < Rr; ++r) {
                float s = g_dinv_out[r * Nn + n];
                uint4 u = pack_half8(hacc[i], s);
                *reinterpret_cast<uint4*>(g_h1s + ((size_t)r * Nn + n) * Dd + tx * 8) = u;
            }
        }
    }
}

// ---------------- layer-2 GEMM + output projection ------------------------------
__launch_bounds__(256)
__global__ void k_gemm2(const float* __restrict__ x, float* __restrict__ out) {
    __shared__ float As[64 * 132];
    __shared__ float Ws[16 * 64];
    int tid = threadIdx.x;
    int ty = tid >> 4, tx = tid & 15;
    int n0 = blockIdx.x << 6;

    float acc[4][4];
#pragma unroll
    for (int i = 0; i < 4; ++i)
#pragma unroll
        for (int j = 0; j < 4; ++j) acc[i][j] = 0.f;

    for (int seg = 0; seg < 4; ++seg) {
        for (int idx = tid; idx < 64 * 32; idx += 256) {
            int row = idx >> 5, c4 = idx & 31;
            int n = n0 + row;
            float4 v = make_float4(0.f, 0.f, 0.f, 0.f);
            if (n < Nn) {
                if (seg < 3) {
                    float di = __ldg(g_dinv_in + seg * Nn + n);
                    float4 a = __ldg(reinterpret_cast<const float4*>(g_agg + ((size_t)(seg * Nn + n)) * Dd) + c4);
                    v.x = a.x * di; v.y = a.y * di; v.z = a.z * di; v.w = a.w * di;
                } else {
                    v = __ldg(reinterpret_cast<const float4*>(x + (size_t)n * Dd) + c4);
                }
            }
            *reinterpret_cast<float4*>(&As[row * 132 + c4 * 4]) = v;
        }
        __syncthreads();

        const float* B = (seg < 3) ? (const float*)(g_G + (size_t)seg * Dd * OUTD)
                                   : (const float*)g_Gx;
        for (int kc = 0; kc < 8; ++kc) {
            {
                int kr = tid >> 4, c4 = tid & 15;
                reinterpret_cast<float4*>(&Ws[kr * 64])[c4] =
                    reinterpret_cast<const float4*>(B + (size_t)(kc * 16 + kr) * OUTD)[c4];
            }
            __syncthreads();
#pragma unroll
            for (int k = 0; k < 16; ++k) {
                float a[4];
#pragma unroll
                for (int i = 0; i < 4; ++i) a[i] = As[(ty * 4 + i) * 132 + kc * 16 + k];
                float4 w = *reinterpret_cast<float4*>(&Ws[k * 64 + tx * 4]);
#pragma unroll
                for (int i = 0; i < 4; ++i) {
                    acc[i][0] += a[i] * w.x; acc[i][1] += a[i] * w.y;
                    acc[i][2] += a[i] * w.z; acc[i][3] += a[i] * w.w;
                }
            }
            __syncthreads();
        }
    }

#pragma unroll
    for (int i = 0; i < 4; ++i) {
        int n = n0 + ty * 4 + i;
        if (n < Nn) {
            float4 o;
            o.x = acc[i][0] + g_c[tx * 4 + 0];
            o.y = acc[i][1] + g_c[tx * 4 + 1];
            o.z = acc[i][2] + g_c[tx * 4 + 2];
            o.w = acc[i][3] + g_c[tx * 4 + 3];
            *reinterpret_cast<float4*>(out + (size_t)n * OUTD + tx * 4) = o;
        }
    }
}

// ---------------- launch ------------------------------------------------------
extern "C" void kernel_launch(void* const* d_in, const int* in_sizes, int n_in,
                              void* d_out, int out_size) {
    const float* x    = (const float*)d_in[0];
    const int*   src  = (const int*)  d_in[1];
    const int*   dst  = (const int*)  d_in[2];
    const float* W1   = (const float*)d_in[3];
    const float* b1   = (const float*)d_in[4];
    const float* W2   = (const float*)d_in[5];
    const float* b2   = (const float*)d_in[6];
    const float* Wlin = (const float*)d_in[7];
    const float* blin = (const float*)d_in[8];
    float* out = (float*)d_out;

    k_init<<<(Rr * Nn + 255) / 256, 256>>>();
    k_degree<<<(Rr * Ee + 255) / 256, 256>>>(src, dst);
    dim3 rsgrid((Nn + 255) / 256, Rr);
    k_rowstart<<<rsgrid, 256>>>();
    k_csrfill<<<(Rr * Ee + 255) / 256, 256>>>(src, dst);
    k_prescale<<<(int)(((size_t)Rr * Nn * (Dd / 4) + 255) / 256), 256>>>(x);
    k_prep1<<<Rr * Dd, OUTD>>>(W2, Wlin);
    k_prep2<<<32, 256>>>(b2, Wlin, blin);

    const int gather_blocks = (Rr * Nn * 32 + 255) / 256;   // one warp per (r,n)
    // layer 1
    k_gather<<<gather_blocks, 256>>>(0);
    k_gemm1<<<(Nn + 63) / 64, 256>>>(x, W1, b1);
    // layer 2
    k_gather<<<gather_blocks, 256>>>(1);
    k_gemm2<<<(Nn + 63) / 64, 256>>>(x, out);
}

// round 6
// speedup vs baseline: 1.5771x; 1.3451x over previous
#include <cuda_runtime.h>
#include <cuda_fp16.h>
#include <mma.h>
#include <cstdint>

using namespace nvcuda;

// Problem constants (fixed by dataset)
#define Nn 50000
#define Dd 128
#define Rr 3
#define Ee 800000
#define OUTD 64
#define ALPHAc 0.5f
#define BETA1c 0.6931471805599453f   // ln 2
#define BETA2c 0.4054651081081644f   // ln 1.5
#define SLOPEc 0.01f

// ---------------- scratch (device globals; no allocations allowed) ----------
__device__ __align__(256) __half g_xs  [(size_t)Rr * Nn * Dd];        // prescaled x (dinv_out)
__device__ __align__(256) __half g_h1s [(size_t)Rr * Nn * Dd];        // prescaled h1 (dinv_out)
__device__ __align__(256) __half g_aggh[((size_t)Rr * Nn + 64) * Dd]; // gather out (dinv_in-scaled), padded
__device__ __align__(256) __half g_xh  [((size_t)Nn + 64) * Dd];      // plain fp16 x, padded
__device__ __align__(256) __half g_W1h [Rr * Dd * Dd];                // b1*W1 + (1-b1)*I
__device__ __align__(256) __half g_Gh  [Rr * Dd * OUTD];
__device__ __align__(256) __half g_Gxh [Dd * OUTD];
__device__ int   g_deg_out[Rr * Nn];
__device__ int   g_deg_in[Rr * Nn];
__device__ float g_dinv_out[Rr * Nn];
__device__ float g_dinv_in[Rr * Nn];
__device__ int   g_rowstart[Rr * Nn];
__device__ int   g_fillcur[Rr * Nn];
__device__ int   g_col[(size_t)Rr * Ee];
__device__ int   g_cursor[Rr];
__device__ float g_G[Rr * Dd * OUTD];
__device__ float g_Gx[Dd * OUTD];
__device__ float g_c[OUTD];

// ---------------- init small state -------------------------------------------
__global__ void k_init() {
    int i = blockIdx.x * blockDim.x + threadIdx.x;
    if (i < Rr * Nn) { g_deg_out[i] = 0; g_deg_in[i] = 0; }
    if (i < Rr) g_cursor[i] = 0;
}

// ---------------- degree histogram -------------------------------------------
__global__ void k_degree(const int* __restrict__ src, const int* __restrict__ dst) {
    int i = blockIdx.x * blockDim.x + threadIdx.x;
    if (i >= Rr * Ee) return;
    int r = i / Ee;
    atomicAdd(&g_deg_out[r * Nn + src[i]], 1);
    atomicAdd(&g_deg_in [r * Nn + dst[i]], 1);
}

// ---------------- row starts via warp-aggregated scan + dinv ------------------
__global__ void k_rowstart() {
    int r = blockIdx.y;
    int n = blockIdx.x * blockDim.x + threadIdx.x;
    int lane = threadIdx.x & 31;
    int d = (n < Nn) ? g_deg_in[r * Nn + n] : 0;
    int incl = d;
#pragma unroll
    for (int o = 1; o < 32; o <<= 1) {
        int v = __shfl_up_sync(0xffffffffu, incl, o);
        if (lane >= o) incl += v;
    }
    int total = __shfl_sync(0xffffffffu, incl, 31);
    int base = 0;
    if (lane == 31) base = atomicAdd(&g_cursor[r], total);
    base = __shfl_sync(0xffffffffu, base, 31);
    if (n < Nn) {
        int start = r * Ee + base + incl - d;
        g_rowstart[r * Nn + n] = start;
        g_fillcur [r * Nn + n] = start;
        int di = d < 1 ? 1 : d;
        g_dinv_in[r * Nn + n] = rsqrtf((float)di);
        int doo = g_deg_out[r * Nn + n]; if (doo < 1) doo = 1;
        g_dinv_out[r * Nn + n] = rsqrtf((float)doo);
    }
}

// ---------------- CSR fill -----------------------------------------------------
__global__ void k_csrfill(const int* __restrict__ src, const int* __restrict__ dst) {
    int i = blockIdx.x * blockDim.x + threadIdx.x;
    if (i >= Rr * Ee) return;
    int r = i / Ee;
    int pos = atomicAdd(&g_fillcur[r * Nn + dst[i]], 1);
    g_col[pos] = src[i];
}

// ---------------- prescale x into fp16 gather operands + plain fp16 x ---------
__global__ void k_prescale(const float* __restrict__ x) {
    size_t i = (size_t)blockIdx.x * blockDim.x + threadIdx.x;   // one per 4 elems
    if (i >= (size_t)Rr * Nn * (Dd / 4)) return;
    int c4 = (int)(i & 31);
    size_t rn = i >> 5;
    int n = (int)(rn % Nn);
    int r = (int)(rn / Nn);
    float s = g_dinv_out[r * Nn + n];
    float4 v = __ldg(reinterpret_cast<const float4*>(x + (size_t)n * Dd) + c4);
    __half2 p0 = __floats2half2_rn(v.x * s, v.y * s);
    __half2 p1 = __floats2half2_rn(v.z * s, v.w * s);
    uint2 u;
    u.x = *reinterpret_cast<unsigned*>(&p0);
    u.y = *reinterpret_cast<unsigned*>(&p1);
    *reinterpret_cast<uint2*>(g_xs + rn * Dd + c4 * 4) = u;
    if (r == 0) {
        __half2 q0 = __floats2half2_rn(v.x, v.y);
        __half2 q1 = __floats2half2_rn(v.z, v.w);
        uint2 w;
        w.x = *reinterpret_cast<unsigned*>(&q0);
        w.y = *reinterpret_cast<unsigned*>(&q1);
        *reinterpret_cast<uint2*>(g_xh + (size_t)n * Dd + c4 * 4) = w;
    }
}

// ---------------- precompute folded layer-2 matrices --------------------------
__global__ void k_prep1(const float* __restrict__ W2, const float* __restrict__ Wlin) {
    int r = blockIdx.x >> 7;
    int i = blockIdx.x & 127;
    int j = threadIdx.x;              // 0..63
    const float* wrow = W2 + ((size_t)r * Dd + i) * Dd;
    float s = 0.f;
#pragma unroll 8
    for (int k = 0; k < Dd; ++k) s += wrow[k] * Wlin[k * OUTD + j];
    g_G[((size_t)r * Dd + i) * OUTD + j] = BETA2c * s + (1.f - BETA2c) * Wlin[i * OUTD + j];
}

__global__ void k_prep2(const float* __restrict__ b2, const float* __restrict__ Wlin,
                        const float* __restrict__ blin) {
    int idx = blockIdx.x * blockDim.x + threadIdx.x;
    if (idx < Dd * OUTD) {
        float s = g_G[idx] + g_G[Dd * OUTD + idx] + g_G[2 * Dd * OUTD + idx];
        g_Gx[idx] = (ALPHAc / 3.f) * s;
        const float sc = (1.f - ALPHAc) / 3.f;
        g_G[idx] *= sc;
        g_G[Dd * OUTD + idx] *= sc;
        g_G[2 * Dd * OUTD + idx] *= sc;
    }
    if (idx < OUTD) {
        float cc = blin[idx];
        for (int k = 0; k < Dd; ++k)
            cc += (b2[k] + b2[Dd + k] + b2[2 * Dd + k]) * (1.f / 3.f) * Wlin[k * OUTD + idx];
        g_c[idx] = cc;
    }
}

// convert G/Gx to fp16
__global__ void k_prep3() {
    int idx = blockIdx.x * blockDim.x + threadIdx.x;
    if (idx < Rr * Dd * OUTD) g_Gh[idx] = __float2half(g_G[idx]);
    if (idx < Dd * OUTD)      g_Gxh[idx] = __float2half(g_Gx[idx]);
}

// W1' = b1*W1 + (1-b1)*I, fp16
__global__ void k_prepw1(const float* __restrict__ W1) {
    int idx = blockIdx.x * blockDim.x + threadIdx.x;
    if (idx >= Rr * Dd * Dd) return;
    int ij = idx % (Dd * Dd);
    int i = ij >> 7, j = ij & 127;
    float v = BETA1c * W1[idx] + ((i == j) ? (1.f - BETA1c) : 0.f);
    g_W1h[idx] = __float2half(v);
}

// ---------------- fp16 gather helpers ------------------------------------------
__device__ __forceinline__ void acc_h4(float4& acc, uint2 u) {
    __half2 a = *reinterpret_cast<__half2*>(&u.x);
    __half2 b = *reinterpret_cast<__half2*>(&u.y);
    float2 fa = __half22float2(a), fb = __half22float2(b);
    acc.x += fa.x; acc.y += fa.y; acc.z += fb.x; acc.w += fb.y;
}

// ---------------- dedicated gather: one warp per (r,n); fp16 scaled out --------
__launch_bounds__(256)
__global__ void k_gather(int which) {
    int gw = (blockIdx.x * blockDim.x + threadIdx.x) >> 5;   // (r,n) index
    if (gw >= Rr * Nn) return;
    int lane = threadIdx.x & 31;
    const __half* base = (which ? g_h1s : g_xs) + (size_t)(gw / Nn) * Nn * Dd;

    int beg = __ldg(g_rowstart + gw);
    int end = beg + __ldg(g_deg_in + gw);
    float4 acc = make_float4(0.f, 0.f, 0.f, 0.f);
    int e = beg;
#pragma unroll 1
    for (; e + 4 <= end; e += 4) {
        int s0 = __ldg(g_col + e);
        int s1 = __ldg(g_col + e + 1);
        int s2 = __ldg(g_col + e + 2);
        int s3 = __ldg(g_col + e + 3);
        uint2 u0 = __ldg(reinterpret_cast<const uint2*>(base + (size_t)s0 * Dd) + lane);
        uint2 u1 = __ldg(reinterpret_cast<const uint2*>(base + (size_t)s1 * Dd) + lane);
        uint2 u2 = __ldg(reinterpret_cast<const uint2*>(base + (size_t)s2 * Dd) + lane);
        uint2 u3 = __ldg(reinterpret_cast<const uint2*>(base + (size_t)s3 * Dd) + lane);
        acc_h4(acc, u0); acc_h4(acc, u1); acc_h4(acc, u2); acc_h4(acc, u3);
    }
#pragma unroll 1
    for (; e < end; ++e) {
        int s0 = __ldg(g_col + e);
        uint2 u0 = __ldg(reinterpret_cast<const uint2*>(base + (size_t)s0 * Dd) + lane);
        acc_h4(acc, u0);
    }
    // scale: layer1 gets (1-a)*dinv_in folded in; layer2 gets dinv_in
    float sc = __ldg(g_dinv_in + gw) * (which ? 1.f : (1.f - ALPHAc));
    __half2 p0 = __floats2half2_rn(acc.x * sc, acc.y * sc);
    __half2 p1 = __floats2half2_rn(acc.z * sc, acc.w * sc);
    uint2 u;
    u.x = *reinterpret_cast<unsigned*>(&p0);
    u.y = *reinterpret_cast<unsigned*>(&p1);
    *reinterpret_cast<uint2*>(g_aggh + (size_t)gw * Dd + lane * 4) = u;
}

// pack 8 scaled floats -> 8 halfs (16B)
__device__ __forceinline__ uint4 pack_half8(const float* v, float s) {
    __half2 p0 = __floats2half2_rn(v[0] * s, v[1] * s);
    __half2 p1 = __floats2half2_rn(v[2] * s, v[3] * s);
    __half2 p2 = __floats2half2_rn(v[4] * s, v[5] * s);
    __half2 p3 = __floats2half2_rn(v[6] * s, v[7] * s);
    uint4 u;
    u.x = *reinterpret_cast<unsigned*>(&p0);
    u.y = *reinterpret_cast<unsigned*>(&p1);
    u.z = *reinterpret_cast<unsigned*>(&p2);
    u.w = *reinterpret_cast<unsigned*>(&p3);
    return u;
}

// ---------------- layer-1 GEMM: tensor cores, residual folded into W1' --------
// As_h = agg_scaled + a*x (fp16); C = As_h @ W1'_r ; epi: +bias, leaky, mean
__launch_bounds__(256)
__global__ void k_gemm1(const float* __restrict__ x, const float* __restrict__ b1) {
    __shared__ __align__(16) unsigned char sb[64 * 132 * 4];   // 33792 B union
    __half* As = reinterpret_cast<__half*>(sb);                 // 64 x 128, stride 136
    float*  Cs = reinterpret_cast<float*>(sb);                  // 64 x 128, stride 132
    int tid = threadIdx.x;
    int warp = tid >> 5;
    int ty = tid >> 4, tx = tid & 15;
    int wr = warp >> 1, wc = warp & 1;
    int n0 = blockIdx.x << 6;

    float hacc[4][8];
#pragma unroll
    for (int i = 0; i < 4; ++i)
#pragma unroll
        for (int j = 0; j < 8; ++j) hacc[i][j] = 0.f;

    for (int r = 0; r < Rr; ++r) {
        // build As (fp16): agg already has (1-a)*dinv_in folded
        for (int idx = tid; idx < 64 * 32; idx += 256) {
            int row = idx >> 5, c4 = idx & 31;
            int n = n0 + row;
            float4 v = make_float4(0.f, 0.f, 0.f, 0.f);
            if (n < Nn) {
                uint2 ah = __ldg(reinterpret_cast<const uint2*>(g_aggh + ((size_t)(r * Nn + n)) * Dd) + c4);
                float4 fa = make_float4(0.f, 0.f, 0.f, 0.f);
                acc_h4(fa, ah);
                float4 xv = __ldg(reinterpret_cast<const float4*>(x + (size_t)n * Dd) + c4);
                v.x = fa.x + ALPHAc * xv.x;
                v.y = fa.y + ALPHAc * xv.y;
                v.z = fa.z + ALPHAc * xv.z;
                v.w = fa.w + ALPHAc * xv.w;
            }
            __half2 p0 = __floats2half2_rn(v.x, v.y);
            __half2 p1 = __floats2half2_rn(v.z, v.w);
            uint2 u;
            u.x = *reinterpret_cast<unsigned*>(&p0);
            u.y = *reinterpret_cast<unsigned*>(&p1);
            *reinterpret_cast<uint2*>(As + row * 136 + c4 * 4) = u;
        }
        __syncthreads();

        // wmma: 64x128 tile; warp (wr,wc) does rows wr*16, cols wc*64 (4 frags)
        wmma::fragment<wmma::accumulator, 16, 16, 16, float> acc[4];
#pragma unroll
        for (int f = 0; f < 4; ++f) wmma::fill_fragment(acc[f], 0.f);
        const __half* Bg = g_W1h + (size_t)r * Dd * Dd;
#pragma unroll
        for (int k = 0; k < 8; ++k) {
            wmma::fragment<wmma::matrix_a, 16, 16, 16, __half, wmma::row_major> af;
            wmma::load_matrix_sync(af, As + (wr * 16) * 136 + k * 16, 136);
#pragma unroll
            for (int f = 0; f < 4; ++f) {
                wmma::fragment<wmma::matrix_b, 16, 16, 16, __half, wmma::row_major> bf;
                wmma::load_matrix_sync(bf, Bg + (k * 16) * Dd + wc * 64 + f * 16, Dd);
                wmma::mma_sync(acc[f], af, bf, acc[f]);
            }
        }
        __syncthreads();   // all warps done reading As before Cs overwrites
#pragma unroll
        for (int f = 0; f < 4; ++f)
            wmma::store_matrix_sync(Cs + (wr * 16) * 132 + wc * 64 + f * 16, acc[f], 132,
                                    wmma::mem_row_major);
        __syncthreads();

        // epilogue: +bias, leaky, 1/3 mean
#pragma unroll
        for (int i = 0; i < 4; ++i) {
            int row = ty * 4 + i;
#pragma unroll
            for (int j = 0; j < 8; ++j) {
                int col = tx * 8 + j;
                float v = Cs[row * 132 + col] + b1[r * Dd + col];
                v = v >= 0.f ? v : SLOPEc * v;
                hacc[i][j] += v * (1.f / 3.f);
            }
        }
        __syncthreads();
    }

    // write prescaled fp16 h1s for each relation
#pragma unroll
    for (int i = 0; i < 4; ++i) {
        int n = n0 + ty * 4 + i;
        if (n < Nn) {
#pragma unroll
            for (int r = 0; r < Rr; ++r) {
                float s = g_dinv_out[r * Nn + n];
                uint4 u = pack_half8(hacc[i], s);
                *reinterpret_cast<uint4*>(g_h1s + ((size_t)r * Nn + n) * Dd + tx * 8) = u;
            }
        }
    }
}

// ---------------- layer-2 GEMM + output projection: tensor cores ----------------
// out = sum_seg A_seg @ B_seg + c ; A frags loaded straight from global fp16
__launch_bounds__(256)
__global__ void k_gemm2(float* __restrict__ out) {
    __shared__ __align__(16) float Cs[64 * 68];   // 17408 B
    int tid = threadIdx.x;
    int warp = tid >> 5;
    int ty = tid >> 4, tx = tid & 15;
    int wr = warp >> 1, wc = warp & 1;
    int n0 = blockIdx.x << 6;

    wmma::fragment<wmma::accumulator, 16, 16, 16, float> acc[2];
#pragma unroll
    for (int f = 0; f < 2; ++f) wmma::fill_fragment(acc[f], 0.f);

#pragma unroll 1
    for (int seg = 0; seg < 4; ++seg) {
        const __half* Ab = (seg < 3) ? (g_aggh + ((size_t)seg * Nn + n0) * Dd)
                                     : (g_xh + (size_t)n0 * Dd);
        const __half* Bb = (seg < 3) ? (g_Gh + (size_t)seg * Dd * OUTD) : g_Gxh;
#pragma unroll
        for (int k = 0; k < 8; ++k) {
            wmma::fragment<wmma::matrix_a, 16, 16, 16, __half, wmma::row_major> af;
            wmma::load_matrix_sync(af, Ab + (size_t)(wr * 16) * Dd + k * 16, Dd);
#pragma unroll
            for (int f = 0; f < 2; ++f) {
                wmma::fragment<wmma::matrix_b, 16, 16, 16, __half, wmma::row_major> bf;
                wmma::load_matrix_sync(bf, Bb + (k * 16) * OUTD + wc * 32 + f * 16, OUTD);
                wmma::mma_sync(acc[f], af, bf, acc[f]);
            }
        }
    }
#pragma unroll
    for (int f = 0; f < 2; ++f)
        wmma::store_matrix_sync(Cs + (wr * 16) * 68 + wc * 32 + f * 16, acc[f], 68,
                                wmma::mem_row_major);
    __syncthreads();

#pragma unroll
    for (int i = 0; i < 4; ++i) {
        int n = n0 + ty * 4 + i;
        if (n < Nn) {
            int row = ty * 4 + i;
            float4 o;
            o.x = Cs[row * 68 + tx * 4 + 0] + g_c[tx * 4 + 0];
            o.y = Cs[row * 68 + tx * 4 + 1] + g_c[tx * 4 + 1];
            o.z = Cs[row * 68 + tx * 4 + 2] + g_c[tx * 4 + 2];
            o.w = Cs[row * 68 + tx * 4 + 3] + g_c[tx * 4 + 3];
            *reinterpret_cast<float4*>(out + (size_t)n * OUTD + tx * 4) = o;
        }
    }
}

// ---------------- launch ------------------------------------------------------
extern "C" void kernel_launch(void* const* d_in, const int* in_sizes, int n_in,
                              void* d_out, int out_size) {
    const float* x    = (const float*)d_in[0];
    const int*   src  = (const int*)  d_in[1];
    const int*   dst  = (const int*)  d_in[2];
    const float* W1   = (const float*)d_in[3];
    const float* b1   = (const float*)d_in[4];
    const float* W2   = (const float*)d_in[5];
    const float* b2   = (const float*)d_in[6];
    const float* Wlin = (const float*)d_in[7];
    const float* blin = (const float*)d_in[8];
    float* out = (float*)d_out;

    k_init<<<(Rr * Nn + 255) / 256, 256>>>();
    k_degree<<<(Rr * Ee + 255) / 256, 256>>>(src, dst);
    dim3 rsgrid((Nn + 255) / 256, Rr);
    k_rowstart<<<rsgrid, 256>>>();
    k_csrfill<<<(Rr * Ee + 255) / 256, 256>>>(src, dst);
    k_prescale<<<(int)(((size_t)Rr * Nn * (Dd / 4) + 255) / 256), 256>>>(x);
    k_prep1<<<Rr * Dd, OUTD>>>(W2, Wlin);
    k_prep2<<<32, 256>>>(b2, Wlin, blin);
    k_prep3<<<(Rr * Dd * OUTD + 255) / 256, 256>>>();
    k_prepw1<<<(Rr * Dd * Dd + 255) / 256, 256>>>(W1);

    const int gather_blocks = (Rr * Nn * 32 + 255) / 256;   // one warp per (r,n)
    // layer 1
    k_gather<<<gather_blocks, 256>>>(0);
    k_gemm1<<<(Nn + 63) / 64, 256>>>(x, b1);
    // layer 2
    k_gather<<<gather_blocks, 256>>>(1);
    k_gemm2<<<(Nn + 63) / 64, 256>>>(out);
}